// round 6
// baseline (speedup 1.0000x reference)
#include <cuda_runtime.h>
#include <cuda_bf16.h>
#include <cfloat>
#include <cstdint>

// Problem constants
#define B_    256
#define N_    100000
#define D_    512
#define A_    256
#define K_    32
#define C_    100
#define EPS_  1e-8f

// GEMM tiling (mma.sync m16n8k16 bf16)
#define GM    256              // M tile = all query rows
#define GN    64               // N tile (keys per CTA)
#define BK    32               // k elems per stage
#define AST   36               // smem row stride (bf16 elems), padded
#define BST   36
#define NTILE 1563             // ceil(100000/64)
#define N_PAD (NTILE * GN)     // 100032
#define CAND  64               // candidate count per row

// ---------------- device scratch ----------------
__device__ float          g_q[B_ * D_];
__device__ __nv_bfloat16  g_qhi[B_ * D_];
__device__ float          g_qn[B_];
__device__ float          g_kn[N_];
__device__ float          g_qwq[B_ * A_];
__device__ __nv_bfloat16  g_simh[(size_t)B_ * N_PAD];  // approx sims (bf16)
__device__ int            g_cand[B_ * CAND];
__device__ int            g_idx[B_ * K_];

// ---------------- kernel 1: relu + qnorm + bf16 convert ----------------
__global__ void relu_qnorm_kernel(const float* __restrict__ qf) {
    int b = blockIdx.x, tid = threadIdx.x;
    float s = 0.f;
    for (int i = tid; i < D_; i += 256) {
        float v = fmaxf(qf[b * D_ + i], 0.f);
        g_q[b * D_ + i] = v;
        g_qhi[b * D_ + i] = __float2bfloat16(v);
        s += v * v;
    }
    for (int o = 16; o; o >>= 1) s += __shfl_down_sync(0xffffffffu, s, o);
    __shared__ float sm[8];
    int lane = tid & 31, wrp = tid >> 5;
    if (lane == 0) sm[wrp] = s;
    __syncthreads();
    if (tid == 0) {
        float t = 0.f;
        #pragma unroll
        for (int w = 0; w < 8; w++) t += sm[w];
        g_qn[b] = sqrtf(t);
    }
}

// ---------------- kernel 2: qWq ----------------
__global__ void qwq_kernel(const float* __restrict__ Wq, const float* __restrict__ bq) {
    int b = blockIdx.x, a = threadIdx.x;
    const float* qrow = g_q + b * D_;
    float acc = bq[a];
    #pragma unroll 4
    for (int d = 0; d < D_; d++) acc += qrow[d] * Wq[d * A_ + a];
    g_qwq[b * A_ + a] = acc;
}

// ---------------- kernel 3: key norms ----------------
__global__ void knorm_kernel(const float* __restrict__ keys) {
    int wrp = threadIdx.x >> 5, lane = threadIdx.x & 31;
    int row = blockIdx.x * 8 + wrp;
    if (row >= N_) return;
    const float4* k4 = (const float4*)(keys + (size_t)row * D_);
    float s = 0.f;
    #pragma unroll
    for (int j = 0; j < 4; j++) {
        float4 v = k4[j * 32 + lane];
        s += v.x * v.x + v.y * v.y + v.z * v.z + v.w * v.w;
    }
    for (int o = 16; o; o >>= 1) s += __shfl_down_sync(0xffffffffu, s, o);
    if (lane == 0) g_kn[row] = sqrtf(s);
}

// ---------------- mma.sync helper ----------------
__device__ __forceinline__ void mma16816(float c[4], const uint32_t a[4],
                                         const uint32_t b[2]) {
    asm volatile(
        "mma.sync.aligned.m16n8k16.row.col.f32.bf16.bf16.f32 "
        "{%0,%1,%2,%3}, {%4,%5,%6,%7}, {%8,%9}, {%0,%1,%2,%3};"
        : "+f"(c[0]), "+f"(c[1]), "+f"(c[2]), "+f"(c[3])
        : "r"(a[0]), "r"(a[1]), "r"(a[2]), "r"(a[3]), "r"(b[0]), "r"(b[1]));
}

// ---------------- kernel 4: approx sim GEMM (bf16 mma.sync) ----------------
// CTA: 256(M) x 64(N), 8 warps as 4(m) x 2(n), warp tile 64x32.
// smem: double-buffered A[256][36] + B[64][36] bf16 = 46080 B (static).
__global__ __launch_bounds__(256) void sim_gemm_kernel(const float* __restrict__ keys) {
    __shared__ __nv_bfloat16 As[2][GM * AST];
    __shared__ __nv_bfloat16 Bs[2][GN * BST];

    int tid = threadIdx.x;
    int wid = tid >> 5, lane = tid & 31;
    int g = lane >> 2, tig = lane & 3;
    int n0cta = blockIdx.x * GN;
    int m0w = (wid >> 1) * 64;
    int n0w = (wid & 1) * 32;

    float c[4][4][4];
    #pragma unroll
    for (int mf = 0; mf < 4; mf++)
        #pragma unroll
        for (int nf = 0; nf < 4; nf++)
            #pragma unroll
            for (int r = 0; r < 4; r++) c[mf][nf][r] = 0.f;

    // ---- prologue: fill stage 0 ----
    // A: 1024 uint4 loads (8 bf16 each); per thread 4
    #pragma unroll
    for (int u = 0; u < 4; u++) {
        int i = tid + u * 256;
        int r = i >> 2, c8 = i & 3;
        uint4 v = *(const uint4*)&g_qhi[r * D_ + c8 * 8];
        *(uint2*)&As[0][r * AST + c8 * 8]     = make_uint2(v.x, v.y);
        *(uint2*)&As[0][r * AST + c8 * 8 + 4] = make_uint2(v.z, v.w);
    }
    // B: 512 float4 loads; per thread 2
    #pragma unroll
    for (int u = 0; u < 2; u++) {
        int i = tid + u * 256;
        int r = i >> 3, c4 = i & 7;
        int n = n0cta + r;
        float4 v = make_float4(0.f, 0.f, 0.f, 0.f);
        if (n < N_) v = *(const float4*)&keys[(size_t)n * D_ + c4 * 4];
        __nv_bfloat162 p0 = __floats2bfloat162_rn(v.x, v.y);
        __nv_bfloat162 p1 = __floats2bfloat162_rn(v.z, v.w);
        *(uint2*)&Bs[0][r * BST + c4 * 4] =
            make_uint2(*(uint32_t*)&p0, *(uint32_t*)&p1);
    }
    __syncthreads();

    const int NSTAGE = D_ / BK;   // 16
    uint4  pa[4];
    float4 pb[2];

    #pragma unroll 1
    for (int t = 0; t < NSTAGE; t++) {
        int cur = t & 1, nxt = cur ^ 1;
        int k1 = (t + 1) * BK;
        bool have_next = (t + 1 < NSTAGE);

        // prefetch next stage into registers (latency hidden under mma)
        if (have_next) {
            #pragma unroll
            for (int u = 0; u < 4; u++) {
                int i = tid + u * 256;
                int r = i >> 2, c8 = i & 3;
                pa[u] = *(const uint4*)&g_qhi[r * D_ + k1 + c8 * 8];
            }
            #pragma unroll
            for (int u = 0; u < 2; u++) {
                int i = tid + u * 256;
                int r = i >> 3, c4 = i & 7;
                int n = n0cta + r;
                pb[u] = (n < N_) ? *(const float4*)&keys[(size_t)n * D_ + k1 + c4 * 4]
                                 : make_float4(0.f, 0.f, 0.f, 0.f);
            }
        }

        // compute: 2 k16 steps on stage cur
        #pragma unroll
        for (int kk = 0; kk < BK; kk += 16) {
            uint32_t a[4][4], b[4][2];
            #pragma unroll
            for (int mf = 0; mf < 4; mf++) {
                int r0 = m0w + mf * 16 + g;
                a[mf][0] = *(const uint32_t*)&As[cur][r0 * AST + kk + 2 * tig];
                a[mf][1] = *(const uint32_t*)&As[cur][(r0 + 8) * AST + kk + 2 * tig];
                a[mf][2] = *(const uint32_t*)&As[cur][r0 * AST + kk + 8 + 2 * tig];
                a[mf][3] = *(const uint32_t*)&As[cur][(r0 + 8) * AST + kk + 8 + 2 * tig];
            }
            #pragma unroll
            for (int nf = 0; nf < 4; nf++) {
                int n0f = n0w + nf * 8 + g;
                b[nf][0] = *(const uint32_t*)&Bs[cur][n0f * BST + kk + 2 * tig];
                b[nf][1] = *(const uint32_t*)&Bs[cur][n0f * BST + kk + 8 + 2 * tig];
            }
            #pragma unroll
            for (int mf = 0; mf < 4; mf++)
                #pragma unroll
                for (int nf = 0; nf < 4; nf++)
                    mma16816(c[mf][nf], a[mf], b[nf]);
        }

        // commit prefetched registers to the other stage
        if (have_next) {
            #pragma unroll
            for (int u = 0; u < 4; u++) {
                int i = tid + u * 256;
                int r = i >> 2, c8 = i & 3;
                *(uint2*)&As[nxt][r * AST + c8 * 8]     = make_uint2(pa[u].x, pa[u].y);
                *(uint2*)&As[nxt][r * AST + c8 * 8 + 4] = make_uint2(pa[u].z, pa[u].w);
            }
            #pragma unroll
            for (int u = 0; u < 2; u++) {
                int i = tid + u * 256;
                int r = i >> 3, c4 = i & 7;
                __nv_bfloat162 p0 = __floats2bfloat162_rn(pb[u].x, pb[u].y);
                __nv_bfloat162 p1 = __floats2bfloat162_rn(pb[u].z, pb[u].w);
                *(uint2*)&Bs[nxt][r * BST + c4 * 4] =
                    make_uint2(*(uint32_t*)&p0, *(uint32_t*)&p1);
            }
        }
        __syncthreads();
    }

    // ---- epilogue: cosine scaling, bf16 store ----
    #pragma unroll
    for (int mf = 0; mf < 4; mf++) {
        int row0 = m0w + mf * 16 + g;
        float qn0 = g_qn[row0], qn1 = g_qn[row0 + 8];
        #pragma unroll
        for (int nf = 0; nf < 4; nf++) {
            int col = n0cta + n0w + nf * 8 + 2 * tig;   // even
            if (col < N_) {                              // col even, N_ even => col+1 < N_
                float kn0 = g_kn[col], kn1 = g_kn[col + 1];
                float d00 = fmaxf(qn0 * kn0, EPS_), d01 = fmaxf(qn0 * kn1, EPS_);
                float d10 = fmaxf(qn1 * kn0, EPS_), d11 = fmaxf(qn1 * kn1, EPS_);
                __nv_bfloat162 v0 = __floats2bfloat162_rn(c[mf][nf][0] / d00,
                                                          c[mf][nf][1] / d01);
                __nv_bfloat162 v1 = __floats2bfloat162_rn(c[mf][nf][2] / d10,
                                                          c[mf][nf][3] / d11);
                *(uint32_t*)&g_simh[(size_t)row0 * N_PAD + col]       = *(uint32_t*)&v0;
                *(uint32_t*)&g_simh[(size_t)(row0 + 8) * N_PAD + col] = *(uint32_t*)&v1;
            }
        }
    }
}

// ---------------- kernel 5: approx top-64 candidates per row ----------------
// Per-thread local top-8 of a 1/256 slice, then 64 block-argmax merge rounds.
// P(true top-64 item missed by local top-8) < 1e-9 (balls-in-bins).
#define LK 8
__global__ __launch_bounds__(256) void topk_kernel() {
    int b = blockIdx.x, tid = threadIdx.x;
    float lv[LK];
    int   li[LK];
    #pragma unroll
    for (int i = 0; i < LK; i++) { lv[i] = -FLT_MAX; li[i] = 0; }

    const __nv_bfloat16* row = g_simh + (size_t)b * N_PAD;
    for (int n = 2 * tid; n < N_; n += 512) {
        __nv_bfloat162 p = *(const __nv_bfloat162*)&row[n];
        float v0 = __bfloat162float(p.x), v1 = __bfloat162float(p.y);
        if (v0 > lv[LK - 1]) {
            int q = LK - 1;
            while (q > 0 && v0 > lv[q - 1]) { lv[q] = lv[q - 1]; li[q] = li[q - 1]; q--; }
            lv[q] = v0; li[q] = n;
        }
        if (v1 > lv[LK - 1]) {
            int q = LK - 1;
            while (q > 0 && v1 > lv[q - 1]) { lv[q] = lv[q - 1]; li[q] = li[q - 1]; q--; }
            lv[q] = v1; li[q] = n + 1;
        }
    }

    __shared__ float sv[256];
    __shared__ int   st[256];
    int p = 0;
    for (int it = 0; it < CAND; it++) {
        sv[tid] = (p < LK) ? lv[p] : -FLT_MAX;
        st[tid] = tid;
        __syncthreads();
        for (int s = 128; s > 0; s >>= 1) {
            if (tid < s) {
                if (sv[tid + s] > sv[tid]) { sv[tid] = sv[tid + s]; st[tid] = st[tid + s]; }
            }
            __syncthreads();
        }
        if (tid == st[0]) {
            g_cand[b * CAND + it] = li[p];
            p++;
        }
        __syncthreads();
    }
}

// ---------------- kernel 6: exact fp32 rescore of 64 candidates -> top-32 set ----
__global__ __launch_bounds__(256) void rescore_kernel(const float* __restrict__ keys) {
    int b = blockIdx.x, tid = threadIdx.x;
    int wid = tid >> 5, lane = tid & 31;
    __shared__ float simv[CAND];
    __shared__ int   cand[CAND];
    __shared__ int   cnt;
    if (tid < CAND) cand[tid] = g_cand[b * CAND + tid];
    if (tid == 0) cnt = 0;
    __syncthreads();

    float qn = g_qn[b];
    const float4* q4 = (const float4*)(g_q + b * D_);
    for (int ci = wid; ci < CAND; ci += 8) {
        int idx = cand[ci];
        const float4* k4 = (const float4*)(keys + (size_t)idx * D_);
        float s = 0.f;
        #pragma unroll
        for (int j = 0; j < 4; j++) {
            float4 qv = q4[j * 32 + lane];
            float4 kv = k4[j * 32 + lane];
            s += qv.x * kv.x + qv.y * kv.y + qv.z * kv.z + qv.w * kv.w;
        }
        for (int o = 16; o; o >>= 1) s += __shfl_down_sync(0xffffffffu, s, o);
        if (lane == 0) simv[ci] = s / fmaxf(qn * g_kn[idx], EPS_);
    }
    __syncthreads();

    // rank by counting; keep top-32 (stable: ties broken by lower slot)
    if (tid < CAND) {
        float v = simv[tid];
        int r = 0;
        #pragma unroll
        for (int j = 0; j < CAND; j++)
            r += (simv[j] > v) || (simv[j] == v && j < tid);
        if (r < K_) {
            int pos = atomicAdd(&cnt, 1);
            g_idx[b * K_ + pos] = cand[tid];
        }
    }
}

// ---------------- kernel 7: attention MLP + softmax + classifier ----------------
__global__ __launch_bounds__(256) void attn_out_kernel(
    const float* __restrict__ keys,
    const float* __restrict__ Wm, const float* __restrict__ bm,
    const float* __restrict__ Ws, const float* __restrict__ bs,
    const float* __restrict__ Wc, const float* __restrict__ bc,
    float* __restrict__ out) {
    int b = blockIdx.x, tid = threadIdx.x;
    __shared__ int   s_idx[K_];
    __shared__ float s_red[8][K_];
    __shared__ float s_w[K_];
    __shared__ float s_att[D_];
    if (tid < K_) s_idx[tid] = g_idx[b * K_ + tid];
    __syncthreads();

    float macc[K_];
    float bma = bm[tid];
    #pragma unroll
    for (int k = 0; k < K_; k++) macc[k] = bma;

    for (int d = 0; d < D_; d += 4) {
        float w0 = Wm[(d + 0) * A_ + tid];
        float w1 = Wm[(d + 1) * A_ + tid];
        float w2 = Wm[(d + 2) * A_ + tid];
        float w3 = Wm[(d + 3) * A_ + tid];
        #pragma unroll
        for (int k = 0; k < K_; k++) {
            float4 kv = *(const float4*)&keys[(size_t)s_idx[k] * D_ + d];
            macc[k] += kv.x * w0 + kv.y * w1 + kv.z * w2 + kv.w * w3;
        }
    }

    float qa  = g_qwq[b * A_ + tid];
    float wsa = Ws[tid];
    int lane = tid & 31, wrp = tid >> 5;
    for (int k = 0; k < K_; k++) {
        float t = tanhf(qa + macc[k]) * wsa;
        for (int o = 16; o; o >>= 1) t += __shfl_down_sync(0xffffffffu, t, o);
        if (lane == 0) s_red[wrp][k] = t;
    }
    __syncthreads();

    if (tid < K_) {
        float s = bs[0];
        #pragma unroll
        for (int w = 0; w < 8; w++) s += s_red[w][tid];
        float m = s;
        for (int o = 16; o; o >>= 1) m = fmaxf(m, __shfl_xor_sync(0xffffffffu, m, o));
        float e = expf(s - m);
        float tot = e;
        for (int o = 16; o; o >>= 1) tot += __shfl_xor_sync(0xffffffffu, tot, o);
        s_w[tid] = e / tot;
    }
    __syncthreads();

    for (int d = tid; d < D_; d += 256) {
        float a = 0.f;
        #pragma unroll
        for (int k = 0; k < K_; k++) a += s_w[k] * keys[(size_t)s_idx[k] * D_ + d];
        s_att[d] = a;
    }
    __syncthreads();

    for (int c = tid; c < C_; c += 256) {
        float acc = bc[c];
        const float* qrow = g_q + b * D_;
        #pragma unroll 4
        for (int j = 0; j < D_; j++) acc += qrow[j] * Wc[j * C_ + c];
        #pragma unroll 4
        for (int j = 0; j < D_; j++) acc += s_att[j] * Wc[(D_ + j) * C_ + c];
        out[b * C_ + c] = acc;
    }
}

// ---------------- launch ----------------
extern "C" void kernel_launch(void* const* d_in, const int* in_sizes, int n_in,
                              void* d_out, int out_size) {
    const float* query_feat = (const float*)d_in[0];
    const float* keys       = (const float*)d_in[1];
    const float* Wq         = (const float*)d_in[2];
    const float* bq         = (const float*)d_in[3];
    const float* Wm         = (const float*)d_in[4];
    const float* bm         = (const float*)d_in[5];
    const float* Ws         = (const float*)d_in[6];
    const float* bs         = (const float*)d_in[7];
    const float* Wc         = (const float*)d_in[8];
    const float* bc         = (const float*)d_in[9];
    float* out = (float*)d_out;

    relu_qnorm_kernel<<<B_, 256>>>(query_feat);
    qwq_kernel<<<B_, A_>>>(Wq, bq);
    knorm_kernel<<<(N_ + 7) / 8, 256>>>(keys);
    sim_gemm_kernel<<<NTILE, 256>>>(keys);
    topk_kernel<<<B_, 256>>>();
    rescore_kernel<<<B_, 256>>>(keys);
    attn_out_kernel<<<B_, 256>>>(keys, Wm, bm, Ws, bs, Wc, bc, out);
}